// round 10
// baseline (speedup 1.0000x reference)
#include <cuda_runtime.h>
#include <math.h>

#define NB   2
#define CI_  256      // output channels of deform conv / input channels of transconv
#define CO_  128      // channels of up
#define H0   64
#define W0   64
#define HH   128
#define WW   128
#define KKT  9
#define KGEMM (CO_*KKT)   // 1152
#define HW   (HH*WW)      // 16384

// ---- scratch (device globals; no allocations anywhere) ----
__device__ float g_up[NB*CO_*HH*WW];          // 16 MB (L2-resident during GEMM)
__device__ float g_A [KGEMM*CI_];             // 1.18 MB, layout [k][o]
__device__ int   g_ab[NB*KKT*2];
__device__ float g_w4[NB*KKT*4];

// ---- packed f32x2 helpers (sm_103a FFMA2 path) ----
__device__ __forceinline__ void ffma2(float2& d, unsigned long long a, unsigned long long b) {
    asm("fma.rn.f32x2 %0, %1, %2, %0;"
        : "+l"(*reinterpret_cast<unsigned long long*>(&d))
        : "l"(a), "l"(b));
}
__device__ __forceinline__ unsigned long long dup2(float a) {
    unsigned long long r;
    asm("mov.b64 %0, {%1, %1};" : "=l"(r) : "f"(a));
    return r;
}

// ============================================================
// 1) offsets: two center-tap matvecs + tanh -> per-(n,kk) bilinear table
// ============================================================
__global__ void offset_kernel(const float* __restrict__ lat_g,
                              const float* __restrict__ w1,
                              const float* __restrict__ b1,
                              const float* __restrict__ w2,
                              const float* __restrict__ b2) {
    __shared__ float lat[NB*CO_];
    __shared__ float hsm[NB*64];
    __shared__ float off[NB*18];
    int t = threadIdx.x;
    if (t < NB*CO_) lat[t] = lat_g[t];
    __syncthreads();
    if (t < NB*64) {
        int n = t >> 6, c = t & 63;
        float s = b1[c];
        const float* lp = &lat[n*CO_];
        #pragma unroll 4
        for (int i = 0; i < CO_; i++) s += lp[i] * w1[c*(CO_*9) + i*9 + 4];
        hsm[t] = fmaxf(s, 0.f);
    }
    __syncthreads();
    if (t < NB*18) {
        int n = t / 18, j = t % 18;
        float s = b2[j];
        const float* hp = &hsm[n*64];
        #pragma unroll 4
        for (int c = 0; c < 64; c++) s += hp[c] * w2[j*(64*9) + c*9 + 4];
        off[n*18 + j] = tanhf(s);
    }
    __syncthreads();
    if (t < NB*KKT) {
        int n  = t / KKT;
        int kk = t % KKT;
        int ky = kk / 3, kx = kk % 3;
        float oy = off[n*18 + kk*2 + 0];
        float ox = off[n*18 + kk*2 + 1];
        float fy = floorf(oy), fx = floorf(ox);
        float dy = oy - fy,    dx = ox - fx;
        g_ab[t*2+0] = ky - 1 + (int)fy;     // a in [-2,1]
        g_ab[t*2+1] = kx - 1 + (int)fx;     // b in [-2,1]
        g_w4[t*4+0] = (1.f-dy)*(1.f-dx);
        g_w4[t*4+1] = (1.f-dy)*dx;
        g_w4[t*4+2] = dy*(1.f-dx);
        g_w4[t*4+3] = dy*dx;
    }
}

// ============================================================
// 2) repack trans_w [o][c][kk] -> A'[k=c*9+kk][o]  (o contiguous)
// ============================================================
__global__ void repack_kernel(const float* __restrict__ tw) {
    int k = blockIdx.x;        // 0..1151
    int o = threadIdx.x;       // 0..255
    g_A[k*CI_ + o] = tw[o*KGEMM + k];
}

// ============================================================
// 3) transposed conv (stride 2, pad 1, out_pad 1) -> g_up
//    parity decomposition: each thread computes 2 output quads (2x2 each)
// ============================================================
__global__ __launch_bounds__(128) void transconv_kernel(const float* __restrict__ x,
                                                        const float* __restrict__ tw) {
    __shared__ float xs[8][17][18];
    __shared__ float ws[8][8][9];
    int n    = blockIdx.z;
    int cob  = blockIdx.y;
    int tile = blockIdx.x;
    int ty0 = (tile >> 2) * 16;
    int tx0 = (tile &  3) * 16;
    int t = threadIdx.x;
    int qx = t & 15, qyb = t >> 4;

    float acc[2][8][4];
    #pragma unroll
    for (int q = 0; q < 2; q++)
        #pragma unroll
        for (int co = 0; co < 8; co++)
            #pragma unroll
            for (int s = 0; s < 4; s++) acc[q][co][s] = 0.f;

    for (int cic = 0; cic < CI_; cic += 8) {
        for (int l = t; l < 8*17*17; l += 128) {
            int ci = l / 289, rem = l % 289, r = rem / 17, s = rem % 17;
            int yy = ty0 + r, xx = tx0 + s;
            float v = 0.f;
            if (yy < H0 && xx < W0)
                v = x[((n*CI_ + cic + ci)*H0 + yy)*W0 + xx];
            xs[ci][r][s] = v;
        }
        for (int l = t; l < 8*8*9; l += 128) {
            int ci = l / 72, rem = l % 72, co = rem / 9, tap = rem % 9;
            ws[ci][co][tap] = tw[(cic+ci)*KGEMM + (cob*8+co)*9 + tap];
        }
        __syncthreads();

        #pragma unroll
        for (int ci = 0; ci < 8; ci++) {
            float Av[2], Bv[2], Cv[2], Dv[2];
            #pragma unroll
            for (int q = 0; q < 2; q++) {
                int qy = qyb + q*8;
                Av[q] = xs[ci][qy  ][qx  ];
                Bv[q] = xs[ci][qy  ][qx+1];
                Cv[q] = xs[ci][qy+1][qx  ];
                Dv[q] = xs[ci][qy+1][qx+1];
            }
            #pragma unroll
            for (int co = 0; co < 8; co++) {
                float u0 = ws[ci][co][0], u1 = ws[ci][co][1], u2 = ws[ci][co][2];
                float u3 = ws[ci][co][3], u4 = ws[ci][co][4], u5 = ws[ci][co][5];
                float u6 = ws[ci][co][6], u7 = ws[ci][co][7], u8 = ws[ci][co][8];
                #pragma unroll
                for (int q = 0; q < 2; q++) {
                    acc[q][co][0] = fmaf(Av[q], u4, acc[q][co][0]);
                    acc[q][co][1] = fmaf(Bv[q], u3, fmaf(Av[q], u5, acc[q][co][1]));
                    acc[q][co][2] = fmaf(Cv[q], u1, fmaf(Av[q], u7, acc[q][co][2]));
                    acc[q][co][3] = fmaf(Dv[q], u0, fmaf(Cv[q], u2,
                                    fmaf(Bv[q], u6, fmaf(Av[q], u8, acc[q][co][3]))));
                }
            }
        }
        __syncthreads();
    }

    #pragma unroll
    for (int q = 0; q < 2; q++) {
        int Y = (ty0 + qyb + q*8) * 2;
        int X = (tx0 + qx) * 2;
        #pragma unroll
        for (int co = 0; co < 8; co++) {
            float* up = &g_up[((n*CO_ + cob*8+co)*HH + Y)*WW + X];
            *(float2*)(up)      = make_float2(acc[q][co][0], acc[q][co][1]);
            *(float2*)(up + WW) = make_float2(acc[q][co][2], acc[q][co][3]);
        }
    }
}

// ============================================================
// 4) fused GEMM: out[n][o][y][:] = sum_k A'[k][o] * S_k(up)[y][:]
//    S synthesized on the fly from L2-resident up (no g_S).
//    Tile: M=128 (o), N=128 (one full image row y), BK=18 (2 channels x 9 taps).
//    256 threads, 8x8 per thread, FFMA2 inner product.
// ============================================================
__global__ __launch_bounds__(256, 2) void gemm_fused_kernel(float* __restrict__ out) {
    __shared__ float As[18][128];      // 9.2 KB
    __shared__ float Bs[18][128];      // 9.2 KB
    __shared__ float R [2][5][132];    // 5.3 KB  up rows y-2..y+2, x -2..129, zero-padded
    __shared__ float wv[KKT][4];
    __shared__ int   av[KKT], bv[KKT];

    int y  = blockIdx.x;               // 0..127  (image row == N-tile)
    int ob = blockIdx.y;               // 0..1    (o block of 128)
    int n  = blockIdx.z;
    int t  = threadIdx.x;
    int tx = t & 15, ty = t >> 4;      // 16 x 16

    if (t < KKT) {
        int id = n*KKT + t;
        av[t] = g_ab[id*2+0];
        bv[t] = g_ab[id*2+1];
        wv[t][0] = g_w4[id*4+0]; wv[t][1] = g_w4[id*4+1];
        wv[t][2] = g_w4[id*4+2]; wv[t][3] = g_w4[id*4+3];
    }

    float2 acc[8][4];
    #pragma unroll
    for (int i = 0; i < 8; i++)
        #pragma unroll
        for (int j = 0; j < 4; j++) acc[i][j] = make_float2(0.f, 0.f);

    __syncthreads();   // av/bv/wv ready

    for (int chunk = 0; chunk < CO_/2; chunk++) {
        int c0    = chunk*2;
        int kbase = chunk*18;

        // stage up rows: 2 channels x 5 rows x 132 cols, zero-padded
        for (int l = t; l < 2*5*132; l += 256) {
            int c_loc = l / 660;
            int rem   = l % 660;
            int d     = rem / 132;
            int j     = rem % 132;
            int ry = y + d - 2;
            int xg = j - 2;
            float v = 0.f;
            if ((unsigned)ry < (unsigned)HH && (unsigned)xg < (unsigned)WW)
                v = g_up[((n*CO_ + c0 + c_loc)*HH + ry)*WW + xg];
            R[c_loc][d][j] = v;
        }
        // load A tile: 18 x 128 (576 float4)
        for (int l = t; l < 576; l += 256) {
            int r  = l >> 5;
            int c4 = (l & 31) << 2;
            *(float4*)&As[r][c4] = *(const float4*)(&g_A[(kbase + r)*CI_ + ob*128 + c4]);
        }
        __syncthreads();

        // synthesize Bs[k][x] = bilinear-shift sample (4 FMA each)
        for (int e = t; e < 18*128; e += 256) {
            int k = e >> 7;
            int x = e & 127;
            int c_loc = (k >= 9) ? 1 : 0;
            int kk    = k - c_loc*9;
            int d0 = av[kk] + 2;           // 0..3
            int j0 = x + bv[kk] + 2;       // 0..130
            float w0 = wv[kk][0], w1 = wv[kk][1], w2 = wv[kk][2], w3 = wv[kk][3];
            Bs[k][x] = fmaf(w0, R[c_loc][d0  ][j0],
                       fmaf(w1, R[c_loc][d0  ][j0+1],
                       fmaf(w2, R[c_loc][d0+1][j0],
                            w3 * R[c_loc][d0+1][j0+1])));
        }
        __syncthreads();

        // MMA: 18 k-steps
        #pragma unroll
        for (int k = 0; k < 18; k++) {
            float a[8];
            *(float4*)&a[0] = *(float4*)&As[k][ty*4];
            *(float4*)&a[4] = *(float4*)&As[k][64 + ty*4];
            ulonglong2 bq0 = *(ulonglong2*)&Bs[k][tx*4];
            ulonglong2 bq1 = *(ulonglong2*)&Bs[k][64 + tx*4];
            #pragma unroll
            for (int i = 0; i < 8; i++) {
                unsigned long long ap = dup2(a[i]);
                ffma2(acc[i][0], ap, bq0.x);
                ffma2(acc[i][1], ap, bq0.y);
                ffma2(acc[i][2], ap, bq1.x);
                ffma2(acc[i][3], ap, bq1.y);
            }
        }
        __syncthreads();   // protect As/Bs/R before next chunk overwrites
    }

    // epilogue
    #pragma unroll
    for (int i = 0; i < 8; i++) {
        int o = ob*128 + ((i < 4) ? (ty*4 + i) : (64 + ty*4 + i - 4));
        float* orow = out + ((size_t)(n*CI_ + o))*HW + (size_t)y*WW;
        *(float2*)(orow + tx*4)          = acc[i][0];
        *(float2*)(orow + tx*4 + 2)      = acc[i][1];
        *(float2*)(orow + 64 + tx*4)     = acc[i][2];
        *(float2*)(orow + 64 + tx*4 + 2) = acc[i][3];
    }
}

// ============================================================
extern "C" void kernel_launch(void* const* d_in, const int* in_sizes, int n_in,
                              void* d_out, int out_size) {
    const float* x   = (const float*)d_in[0];  // [2,256,64,64]
    const float* lat = (const float*)d_in[1];  // [2,128,1,1]
    const float* tw  = (const float*)d_in[2];  // [256,128,3,3]
    const float* w1  = (const float*)d_in[3];  // [64,128,3,3]
    const float* b1  = (const float*)d_in[4];  // [64]
    const float* w2  = (const float*)d_in[5];  // [18,64,3,3]
    const float* b2  = (const float*)d_in[6];  // [18]
    float* out = (float*)d_out;                // [2,256,128,128]

    offset_kernel<<<1, 256>>>(lat, w1, b1, w2, b2);
    repack_kernel<<<KGEMM, 256>>>(tw);
    transconv_kernel<<<dim3(16, 16, NB), 128>>>(x, tw);
    gemm_fused_kernel<<<dim3(128, 2, NB), 256>>>(out);
}

// round 13
// speedup vs baseline: 1.3420x; 1.3420x over previous
#include <cuda_runtime.h>
#include <math.h>

#define NB   2
#define CI_  256
#define CO_  128
#define H0   64
#define W0   64
#define HH   128
#define WW   128
#define KKT  9
#define KGEMM (CO_*KKT)   // 1152
#define HW   (HH*WW)      // 16384

// ---- scratch (device globals; no allocations anywhere) ----
__device__ float g_up[NB*CO_*HH*WW];              // 16 MB
__device__ float g_S [(size_t)NB*CO_*KKT*HH*WW];  // 151 MB
__device__ float g_A [KGEMM*CI_];                 // 1.18 MB, layout [k][o]
__device__ int   g_ab[NB*KKT*2];
__device__ float g_w4[NB*KKT*4];

// ---- packed f32x2 helpers (sm_103a FFMA2: full-rate fp32, vs half-rate 3-reg FFMA) ----
__device__ __forceinline__ void ffma2(float2& d, unsigned long long a, unsigned long long b) {
    asm("fma.rn.f32x2 %0, %1, %2, %0;"
        : "+l"(*reinterpret_cast<unsigned long long*>(&d))
        : "l"(a), "l"(b));
}
__device__ __forceinline__ unsigned long long dup2(float a) {
    unsigned long long r;
    asm("mov.b64 %0, {%1, %1};" : "=l"(r) : "f"(a));
    return r;
}

// ============================================================
// 1) offsets
// ============================================================
__global__ void offset_kernel(const float* __restrict__ lat_g,
                              const float* __restrict__ w1,
                              const float* __restrict__ b1,
                              const float* __restrict__ w2,
                              const float* __restrict__ b2) {
    __shared__ float lat[NB*CO_];
    __shared__ float hsm[NB*64];
    __shared__ float off[NB*18];
    int t = threadIdx.x;
    if (t < NB*CO_) lat[t] = lat_g[t];
    __syncthreads();
    if (t < NB*64) {
        int n = t >> 6, c = t & 63;
        float s = b1[c];
        const float* lp = &lat[n*CO_];
        #pragma unroll 4
        for (int i = 0; i < CO_; i++) s += lp[i] * w1[c*(CO_*9) + i*9 + 4];
        hsm[t] = fmaxf(s, 0.f);
    }
    __syncthreads();
    if (t < NB*18) {
        int n = t / 18, j = t % 18;
        float s = b2[j];
        const float* hp = &hsm[n*64];
        #pragma unroll 4
        for (int c = 0; c < 64; c++) s += hp[c] * w2[j*(64*9) + c*9 + 4];
        off[n*18 + j] = tanhf(s);
    }
    __syncthreads();
    if (t < NB*KKT) {
        int n  = t / KKT;
        int kk = t % KKT;
        int ky = kk / 3, kx = kk % 3;
        float oy = off[n*18 + kk*2 + 0];
        float ox = off[n*18 + kk*2 + 1];
        float fy = floorf(oy), fx = floorf(ox);
        float dy = oy - fy,    dx = ox - fx;
        g_ab[t*2+0] = ky - 1 + (int)fy;
        g_ab[t*2+1] = kx - 1 + (int)fx;
        g_w4[t*4+0] = (1.f-dy)*(1.f-dx);
        g_w4[t*4+1] = (1.f-dy)*dx;
        g_w4[t*4+2] = dy*(1.f-dx);
        g_w4[t*4+3] = dy*dx;
    }
}

// ============================================================
// 2) repack trans_w [o][c][kk] -> A'[k][o]
// ============================================================
__global__ void repack_kernel(const float* __restrict__ tw) {
    int k = blockIdx.x;
    int o = threadIdx.x;
    g_A[k*CI_ + o] = tw[o*KGEMM + k];
}

// ============================================================
// 3) transposed conv (parity decomposition) -> g_up   [unchanged, proven]
// ============================================================
__global__ __launch_bounds__(128) void transconv_kernel(const float* __restrict__ x,
                                                        const float* __restrict__ tw) {
    __shared__ float xs[8][17][18];
    __shared__ float ws[8][8][9];
    int n    = blockIdx.z;
    int cob  = blockIdx.y;
    int tile = blockIdx.x;
    int ty0 = (tile >> 2) * 16;
    int tx0 = (tile &  3) * 16;
    int t = threadIdx.x;
    int qx = t & 15, qyb = t >> 4;

    float acc[2][8][4];
    #pragma unroll
    for (int q = 0; q < 2; q++)
        #pragma unroll
        for (int co = 0; co < 8; co++)
            #pragma unroll
            for (int s = 0; s < 4; s++) acc[q][co][s] = 0.f;

    for (int cic = 0; cic < CI_; cic += 8) {
        for (int l = t; l < 8*17*17; l += 128) {
            int ci = l / 289, rem = l % 289, r = rem / 17, s = rem % 17;
            int yy = ty0 + r, xx = tx0 + s;
            float v = 0.f;
            if (yy < H0 && xx < W0)
                v = x[((n*CI_ + cic + ci)*H0 + yy)*W0 + xx];
            xs[ci][r][s] = v;
        }
        for (int l = t; l < 8*8*9; l += 128) {
            int ci = l / 72, rem = l % 72, co = rem / 9, tap = rem % 9;
            ws[ci][co][tap] = tw[(cic+ci)*KGEMM + (cob*8+co)*9 + tap];
        }
        __syncthreads();

        #pragma unroll
        for (int ci = 0; ci < 8; ci++) {
            float Av[2], Bv[2], Cv[2], Dv[2];
            #pragma unroll
            for (int q = 0; q < 2; q++) {
                int qy = qyb + q*8;
                Av[q] = xs[ci][qy  ][qx  ];
                Bv[q] = xs[ci][qy  ][qx+1];
                Cv[q] = xs[ci][qy+1][qx  ];
                Dv[q] = xs[ci][qy+1][qx+1];
            }
            #pragma unroll
            for (int co = 0; co < 8; co++) {
                float u0 = ws[ci][co][0], u1 = ws[ci][co][1], u2 = ws[ci][co][2];
                float u3 = ws[ci][co][3], u4 = ws[ci][co][4], u5 = ws[ci][co][5];
                float u6 = ws[ci][co][6], u7 = ws[ci][co][7], u8 = ws[ci][co][8];
                #pragma unroll
                for (int q = 0; q < 2; q++) {
                    acc[q][co][0] = fmaf(Av[q], u4, acc[q][co][0]);
                    acc[q][co][1] = fmaf(Bv[q], u3, fmaf(Av[q], u5, acc[q][co][1]));
                    acc[q][co][2] = fmaf(Cv[q], u1, fmaf(Av[q], u7, acc[q][co][2]));
                    acc[q][co][3] = fmaf(Dv[q], u0, fmaf(Cv[q], u2,
                                    fmaf(Bv[q], u6, fmaf(Av[q], u8, acc[q][co][3]))));
                }
            }
        }
        __syncthreads();
    }

    #pragma unroll
    for (int q = 0; q < 2; q++) {
        int Y = (ty0 + qyb + q*8) * 2;
        int X = (tx0 + qx) * 2;
        #pragma unroll
        for (int co = 0; co < 8; co++) {
            float* up = &g_up[((n*CO_ + cob*8+co)*HH + Y)*WW + X];
            *(float2*)(up)      = make_float2(acc[q][co][0], acc[q][co][1]);
            *(float2*)(up + WW) = make_float2(acc[q][co][2], acc[q][co][3]);
        }
    }
}

// ============================================================
// 4) build S: 4 outputs per thread, float4 store (was issue-bound at 1/thread)
// ============================================================
__global__ __launch_bounds__(256) void build_s_kernel() {
    int nc = blockIdx.z;               // n*128 + c
    int n  = nc >> 7;
    int kk = blockIdx.y;
    int t  = threadIdx.x;
    int y  = blockIdx.x*8 + (t >> 5);  // 8 rows per block
    int x0 = (t & 31) * 4;             // 4 consecutive x per thread
    int id = n*KKT + kk;
    int a = g_ab[id*2], b = g_ab[id*2+1];
    float w00 = g_w4[id*4+0], w01 = g_w4[id*4+1];
    float w10 = g_w4[id*4+2], w11 = g_w4[id*4+3];
    const float* up = &g_up[(size_t)nc*HW];

    int yy = y + a;
    bool y0ok = (unsigned)yy     < (unsigned)HH;
    bool y1ok = (unsigned)(yy+1) < (unsigned)HH;
    const float* r0 = up + yy*WW;
    const float* r1 = r0 + WW;

    float l0[5], l1[5];
    #pragma unroll
    for (int j = 0; j < 5; j++) {
        int xx = x0 + b + j;
        bool xok = (unsigned)xx < (unsigned)WW;
        l0[j] = (y0ok && xok) ? r0[xx] : 0.f;
        l1[j] = (y1ok && xok) ? r1[xx] : 0.f;
    }
    float4 r;
    r.x = fmaf(w00,l0[0], fmaf(w01,l0[1], fmaf(w10,l1[0], w11*l1[1])));
    r.y = fmaf(w00,l0[1], fmaf(w01,l0[2], fmaf(w10,l1[1], w11*l1[2])));
    r.z = fmaf(w00,l0[2], fmaf(w01,l0[3], fmaf(w10,l1[2], w11*l1[3])));
    r.w = fmaf(w00,l0[3], fmaf(w01,l0[4], fmaf(w10,l1[3], w11*l1[4])));
    *(float4*)&g_S[((size_t)nc*KKT + kk)*HW + y*WW + x0] = r;
}

// ============================================================
// 5) GEMM with FFMA2 + register-prefetch double buffering
//    M=256, N=16384, K=1152 per batch. 64x128 tile, 128 thr, 8x8/thread.
// ============================================================
__global__ __launch_bounds__(128) void gemm_kernel(float* __restrict__ out) {
    __shared__ float As[16][64];
    __shared__ float Bs[16][128];
    int n  = blockIdx.z;
    int ob = blockIdx.y;               // 4 o-blocks of 64
    int pb = blockIdx.x;               // 128 p-blocks of 128
    int t  = threadIdx.x;
    int tx = t & 15, ty = t >> 4;      // 16 x 8
    const float* Ag = g_A + ob*64;
    const float* Bg = g_S + (size_t)n*KGEMM*HW + pb*128;

    float2 acc[8][4];
    #pragma unroll
    for (int i = 0; i < 8; i++)
        #pragma unroll
        for (int j = 0; j < 4; j++) acc[i][j] = make_float2(0.f, 0.f);

    // prefetch registers
    float4 pa[2], pbuf[4];
    int ar[2], ac[2], br[4], bc[4];
    #pragma unroll
    for (int i = 0; i < 2; i++) {
        int f4 = t + i*128;
        ar[i] = f4 >> 4; ac[i] = (f4 & 15) << 2;
    }
    #pragma unroll
    for (int i = 0; i < 4; i++) {
        int f4 = t + i*128;
        br[i] = f4 >> 5; bc[i] = (f4 & 31) << 2;
    }

    // load stage 0
    #pragma unroll
    for (int i = 0; i < 2; i++) pa[i]   = *(const float4*)(Ag + ar[i]*CI_ + ac[i]);
    #pragma unroll
    for (int i = 0; i < 4; i++) pbuf[i] = *(const float4*)(Bg + (size_t)br[i]*HW + bc[i]);
    #pragma unroll
    for (int i = 0; i < 2; i++) *(float4*)&As[ar[i]][ac[i]] = pa[i];
    #pragma unroll
    for (int i = 0; i < 4; i++) *(float4*)&Bs[br[i]][bc[i]] = pbuf[i];

    for (int k0 = 16; k0 <= KGEMM; k0 += 16) {
        __syncthreads();
        // issue next-stage global loads (hidden behind compute)
        if (k0 < KGEMM) {
            #pragma unroll
            for (int i = 0; i < 2; i++) pa[i]   = *(const float4*)(Ag + (k0+ar[i])*CI_ + ac[i]);
            #pragma unroll
            for (int i = 0; i < 4; i++) pbuf[i] = *(const float4*)(Bg + (size_t)(k0+br[i])*HW + bc[i]);
        }
        // compute current stage (FFMA2)
        #pragma unroll
        for (int k = 0; k < 16; k++) {
            float a[8];
            *(float4*)&a[0] = *(float4*)&As[k][ty*4];
            *(float4*)&a[4] = *(float4*)&As[k][32 + ty*4];
            ulonglong2 bq0 = *(ulonglong2*)&Bs[k][tx*4];
            ulonglong2 bq1 = *(ulonglong2*)&Bs[k][64 + tx*4];
            #pragma unroll
            for (int i = 0; i < 8; i++) {
                unsigned long long ap = dup2(a[i]);
                ffma2(acc[i][0], ap, bq0.x);
                ffma2(acc[i][1], ap, bq0.y);
                ffma2(acc[i][2], ap, bq1.x);
                ffma2(acc[i][3], ap, bq1.y);
            }
        }
        __syncthreads();
        if (k0 < KGEMM) {
            #pragma unroll
            for (int i = 0; i < 2; i++) *(float4*)&As[ar[i]][ac[i]] = pa[i];
            #pragma unroll
            for (int i = 0; i < 4; i++) *(float4*)&Bs[br[i]][bc[i]] = pbuf[i];
        }
    }

    #pragma unroll
    for (int i = 0; i < 8; i++) {
        int o = ob*64 + ((i < 4) ? (ty*4 + i) : (32 + ty*4 + i - 4));
        float* orow = out + ((size_t)(n*CI_ + o))*HW + pb*128;
        float4 v0 = make_float4(acc[i][0].x, acc[i][0].y, acc[i][1].x, acc[i][1].y);
        float4 v1 = make_float4(acc[i][2].x, acc[i][2].y, acc[i][3].x, acc[i][3].y);
        *(float4*)(orow + tx*4)      = v0;
        *(float4*)(orow + 64 + tx*4) = v1;
    }
}

// ============================================================
extern "C" void kernel_launch(void* const* d_in, const int* in_sizes, int n_in,
                              void* d_out, int out_size) {
    const float* x   = (const float*)d_in[0];
    const float* lat = (const float*)d_in[1];
    const float* tw  = (const float*)d_in[2];
    const float* w1  = (const float*)d_in[3];
    const float* b1  = (const float*)d_in[4];
    const float* w2  = (const float*)d_in[5];
    const float* b2  = (const float*)d_in[6];
    float* out = (float*)d_out;

    offset_kernel<<<1, 256>>>(lat, w1, b1, w2, b2);
    repack_kernel<<<KGEMM, 256>>>(tw);
    transconv_kernel<<<dim3(16, 16, NB), 128>>>(x, tw);
    build_s_kernel<<<dim3(16, KKT, NB*CO_), 256>>>();
    gemm_kernel<<<dim3(128, 4, NB), 128>>>(out);
}

// round 16
// speedup vs baseline: 1.4788x; 1.1019x over previous
#include <cuda_runtime.h>
#include <cuda_bf16.h>
#include <math.h>
#include <stdint.h>

#define NB   2
#define CI_  256
#define CO_  128
#define H0   64
#define W0   64
#define HH   128
#define WW   128
#define KKT  9
#define KGEMM (CO_*KKT)   // 1152
#define HW   (HH*WW)      // 16384

// ---- scratch (device globals; no allocations anywhere) ----
__device__ float g_up[NB*CO_*HH*WW];                         // 16 MB
__device__ __nv_bfloat16 g_Sh[(size_t)NB*HW*KGEMM];          // 75.5 MB  St hi  [p][k] K-major
__device__ __nv_bfloat16 g_Sl[(size_t)NB*HW*KGEMM];          // 75.5 MB  St lo
__device__ __nv_bfloat16 g_Ah[CI_*KGEMM];                    // 0.59 MB  W hi [o][k]
__device__ __nv_bfloat16 g_Al[CI_*KGEMM];                    // 0.59 MB  W lo
__device__ int   g_ab[NB*KKT*2];
__device__ float g_w4[NB*KKT*4];

// ======================= PTX helpers (baseline ISA only, sm_80+) =======================
__device__ __forceinline__ uint32_t smem_u32(const void* p) {
    uint32_t a;
    asm("{ .reg .u64 t; cvta.to.shared.u64 t, %1; cvt.u32.u64 %0, t; }" : "=r"(a) : "l"(p));
    return a;
}
__device__ __forceinline__ void cp_async16(uint32_t dst, const void* src) {
    asm volatile("cp.async.cg.shared.global [%0], [%1], 16;" :: "r"(dst), "l"(src));
}
__device__ __forceinline__ void ldsm_x4(uint32_t* r, uint32_t addr) {
    asm volatile("ldmatrix.sync.aligned.m8n8.x4.shared.b16 {%0,%1,%2,%3}, [%4];"
        : "=r"(r[0]), "=r"(r[1]), "=r"(r[2]), "=r"(r[3]) : "r"(addr));
}
__device__ __forceinline__ void mma_bf16(float* d, const uint32_t* a, const uint32_t* b) {
    asm volatile("mma.sync.aligned.m16n8k16.row.col.f32.bf16.bf16.f32 "
        "{%0,%1,%2,%3}, {%4,%5,%6,%7}, {%8,%9}, {%0,%1,%2,%3};"
        : "+f"(d[0]), "+f"(d[1]), "+f"(d[2]), "+f"(d[3])
        : "r"(a[0]), "r"(a[1]), "r"(a[2]), "r"(a[3]), "r"(b[0]), "r"(b[1]));
}

// ============================================================
// 1) offsets
// ============================================================
__global__ void offset_kernel(const float* __restrict__ lat_g,
                              const float* __restrict__ w1,
                              const float* __restrict__ b1,
                              const float* __restrict__ w2,
                              const float* __restrict__ b2) {
    __shared__ float lat[NB*CO_];
    __shared__ float hsm[NB*64];
    __shared__ float off[NB*18];
    int t = threadIdx.x;
    if (t < NB*CO_) lat[t] = lat_g[t];
    __syncthreads();
    if (t < NB*64) {
        int n = t >> 6, c = t & 63;
        float s = b1[c];
        const float* lp = &lat[n*CO_];
        #pragma unroll 4
        for (int i = 0; i < CO_; i++) s += lp[i] * w1[c*(CO_*9) + i*9 + 4];
        hsm[t] = fmaxf(s, 0.f);
    }
    __syncthreads();
    if (t < NB*18) {
        int n = t / 18, j = t % 18;
        float s = b2[j];
        const float* hp = &hsm[n*64];
        #pragma unroll 4
        for (int c = 0; c < 64; c++) s += hp[c] * w2[j*(64*9) + c*9 + 4];
        off[n*18 + j] = tanhf(s);
    }
    __syncthreads();
    if (t < NB*KKT) {
        int n  = t / KKT;
        int kk = t % KKT;
        int ky = kk / 3, kx = kk % 3;
        float oy = off[n*18 + kk*2 + 0];
        float ox = off[n*18 + kk*2 + 1];
        float fy = floorf(oy), fx = floorf(ox);
        float dy = oy - fy,    dx = ox - fx;
        g_ab[t*2+0] = ky - 1 + (int)fy;
        g_ab[t*2+1] = kx - 1 + (int)fx;
        g_w4[t*4+0] = (1.f-dy)*(1.f-dx);
        g_w4[t*4+1] = (1.f-dy)*dx;
        g_w4[t*4+2] = dy*(1.f-dx);
        g_w4[t*4+3] = dy*dx;
    }
}

// ============================================================
// 2) split trans_w [o][k] fp32 -> Ah/Al [o][k] bf16 (hi + residual)
// ============================================================
__global__ void split_a_kernel(const float* __restrict__ tw) {
    int o = blockIdx.x;
    for (int k = threadIdx.x; k < KGEMM; k += blockDim.x) {
        float w = tw[o*KGEMM + k];
        __nv_bfloat16 h = __float2bfloat16(w);
        __nv_bfloat16 l = __float2bfloat16(w - __bfloat162float(h));
        g_Ah[o*KGEMM + k] = h;
        g_Al[o*KGEMM + k] = l;
    }
}

// ============================================================
// 3) transposed conv (parity decomposition) -> g_up   [unchanged, proven]
// ============================================================
__global__ __launch_bounds__(128) void transconv_kernel(const float* __restrict__ x,
                                                        const float* __restrict__ tw) {
    __shared__ float xs[8][17][18];
    __shared__ float ws[8][8][9];
    int n    = blockIdx.z;
    int cob  = blockIdx.y;
    int tile = blockIdx.x;
    int ty0 = (tile >> 2) * 16;
    int tx0 = (tile &  3) * 16;
    int t = threadIdx.x;
    int qx = t & 15, qyb = t >> 4;

    float acc[2][8][4];
    #pragma unroll
    for (int q = 0; q < 2; q++)
        #pragma unroll
        for (int co = 0; co < 8; co++)
            #pragma unroll
            for (int s = 0; s < 4; s++) acc[q][co][s] = 0.f;

    for (int cic = 0; cic < CI_; cic += 8) {
        for (int l = t; l < 8*17*17; l += 128) {
            int ci = l / 289, rem = l % 289, r = rem / 17, s = rem % 17;
            int yy = ty0 + r, xx = tx0 + s;
            float v = 0.f;
            if (yy < H0 && xx < W0)
                v = x[((n*CI_ + cic + ci)*H0 + yy)*W0 + xx];
            xs[ci][r][s] = v;
        }
        for (int l = t; l < 8*8*9; l += 128) {
            int ci = l / 72, rem = l % 72, co = rem / 9, tap = rem % 9;
            ws[ci][co][tap] = tw[(cic+ci)*KGEMM + (cob*8+co)*9 + tap];
        }
        __syncthreads();

        #pragma unroll
        for (int ci = 0; ci < 8; ci++) {
            float Av[2], Bv[2], Cv[2], Dv[2];
            #pragma unroll
            for (int q = 0; q < 2; q++) {
                int qy = qyb + q*8;
                Av[q] = xs[ci][qy  ][qx  ];
                Bv[q] = xs[ci][qy  ][qx+1];
                Cv[q] = xs[ci][qy+1][qx  ];
                Dv[q] = xs[ci][qy+1][qx+1];
            }
            #pragma unroll
            for (int co = 0; co < 8; co++) {
                float u0 = ws[ci][co][0], u1 = ws[ci][co][1], u2 = ws[ci][co][2];
                float u3 = ws[ci][co][3], u4 = ws[ci][co][4], u5 = ws[ci][co][5];
                float u6 = ws[ci][co][6], u7 = ws[ci][co][7], u8 = ws[ci][co][8];
                #pragma unroll
                for (int q = 0; q < 2; q++) {
                    acc[q][co][0] = fmaf(Av[q], u4, acc[q][co][0]);
                    acc[q][co][1] = fmaf(Bv[q], u3, fmaf(Av[q], u5, acc[q][co][1]));
                    acc[q][co][2] = fmaf(Cv[q], u1, fmaf(Av[q], u7, acc[q][co][2]));
                    acc[q][co][3] = fmaf(Dv[q], u0, fmaf(Cv[q], u2,
                                    fmaf(Bv[q], u6, fmaf(Av[q], u8, acc[q][co][3]))));
                }
            }
        }
        __syncthreads();
    }

    #pragma unroll
    for (int q = 0; q < 2; q++) {
        int Y = (ty0 + qyb + q*8) * 2;
        int X = (tx0 + qx) * 2;
        #pragma unroll
        for (int co = 0; co < 8; co++) {
            float* up = &g_up[((n*CO_ + cob*8+co)*HH + Y)*WW + X];
            *(float2*)(up)      = make_float2(acc[q][co][0], acc[q][co][1]);
            *(float2*)(up + WW) = make_float2(acc[q][co][2], acc[q][co][3]);
        }
    }
}

// ============================================================
// 4) build St (transposed, K-major, bf16 hi/lo)
//    St[n*HW + y*128 + p][c*9+kk] = bilinear sample of up[n][c] at (y,p)
// ============================================================
__global__ __launch_bounds__(128) void build_st_kernel() {
    __shared__ float R[8][5][132];
    __shared__ float wv[KKT][4];
    __shared__ int   av[KKT], bv[KKT];

    int y  = blockIdx.x;
    int cc = blockIdx.y;          // channel chunk (8 ch)
    int n  = blockIdx.z;
    int t  = threadIdx.x;         // pixel p
    int c0 = cc * 8;

    if (t < KKT) {
        int id = n*KKT + t;
        av[t] = g_ab[id*2+0];
        bv[t] = g_ab[id*2+1];
        wv[t][0] = g_w4[id*4+0]; wv[t][1] = g_w4[id*4+1];
        wv[t][2] = g_w4[id*4+2]; wv[t][3] = g_w4[id*4+3];
    }
    for (int l = t; l < 8*5*132; l += 128) {
        int c = l / 660, rem = l % 660, d = rem / 132, j = rem % 132;
        int ry = y + d - 2, xg = j - 2;
        float v = 0.f;
        if ((unsigned)ry < (unsigned)HH && (unsigned)xg < (unsigned)WW)
            v = g_up[((n*CO_ + c0 + c)*HH + ry)*WW + xg];
        R[c][d][j] = v;
    }
    __syncthreads();

    uint32_t hbuf[36], lbuf[36];
    #pragma unroll
    for (int c = 0; c < 8; c++) {
        #pragma unroll
        for (int kk = 0; kk < 9; kk++) {
            int d0 = av[kk] + 2;
            int j0 = t + bv[kk] + 2;
            float s = fmaf(wv[kk][0], R[c][d0  ][j0],
                      fmaf(wv[kk][1], R[c][d0  ][j0+1],
                      fmaf(wv[kk][2], R[c][d0+1][j0],
                           wv[kk][3]* R[c][d0+1][j0+1])));
            __nv_bfloat16 h = __float2bfloat16(s);
            __nv_bfloat16 l = __float2bfloat16(s - __bfloat162float(h));
            unsigned short hu = *(unsigned short*)&h;
            unsigned short lu = *(unsigned short*)&l;
            int k = c*9 + kk;
            if (k & 1) { hbuf[k>>1] |= (uint32_t)hu << 16; lbuf[k>>1] |= (uint32_t)lu << 16; }
            else       { hbuf[k>>1]  = hu;                 lbuf[k>>1]  = lu; }
        }
    }

    size_t rowbase = ((size_t)(n*HW + y*128 + t))*KGEMM + c0*9;
    uint4* hdst = (uint4*)&g_Sh[rowbase];
    uint4* ldst = (uint4*)&g_Sl[rowbase];
    #pragma unroll
    for (int q = 0; q < 9; q++) {
        hdst[q] = make_uint4(hbuf[q*4], hbuf[q*4+1], hbuf[q*4+2], hbuf[q*4+3]);
        ldst[q] = make_uint4(lbuf[q*4], lbuf[q*4+1], lbuf[q*4+2], lbuf[q*4+3]);
    }
}

// ============================================================
// 5) mma.sync bf16 GEMM, 3-term split: out = Ah·Sh + Ah·Sl + Al·Sh
//    CTA 128(o) x 128(p), BK=32, 8 warps (2x4), warp tile 64x32.
//    3-stage cp.async ring, XOR-swizzled 16B chunks for ldmatrix.
// ============================================================
#define STAGES 3
#define NCH 108                 // 3 passes * (1152/32)
#define STAGE_BYTES 16384       // A 8K + B 8K
#define MMA_SMEM (STAGES*STAGE_BYTES)   // 49152

__global__ __launch_bounds__(256, 2) void mma_kernel(float* __restrict__ out) {
    extern __shared__ char smem[];
    uint32_t smb = smem_u32(smem);
    int t = threadIdx.x, lane = t & 31, w = t >> 5;
    int wm = w >> 2, wn = w & 3;           // 2 x 4 warp grid
    int p0 = blockIdx.x * 128;
    int ob = blockIdx.y;                   // o-block of 128
    int n  = blockIdx.z;

    const size_t Aoff = (size_t)ob*128*KGEMM;
    const size_t Boff = (size_t)(n*HW + p0)*KGEMM;

    // per-thread load slots: 2 chunks each for A and B per stage
    int rowA[2], colA[2];
    #pragma unroll
    for (int i = 0; i < 2; i++) {
        int u = t + i*256;                 // 0..511
        rowA[i] = u >> 2; colA[i] = u & 3; // 128 rows x 4 chunks(16B)
    }

    auto load_stage = [&](int ch) {
        int pass = ch / 36, k0 = (ch % 36) * 32;
        const __nv_bfloat16* As = ((pass == 2) ? g_Al : g_Ah) + Aoff;
        const __nv_bfloat16* Bs = ((pass == 1) ? g_Sl : g_Sh) + Boff;
        uint32_t sA = smb + (ch % STAGES) * STAGE_BYTES;
        uint32_t sB = sA + 8192;
        #pragma unroll
        for (int i = 0; i < 2; i++) {
            int row = rowA[i], c = colA[i];
            uint32_t sw = ((uint32_t)(c ^ (row & 3))) << 4;
            cp_async16(sA + row*64 + sw, As + (size_t)row*KGEMM + k0 + c*8);
            cp_async16(sB + row*64 + sw, Bs + (size_t)row*KGEMM + k0 + c*8);
        }
        asm volatile("cp.async.commit_group;");
    };

    float acc[4][4][4];
    #pragma unroll
    for (int mt = 0; mt < 4; mt++)
        #pragma unroll
        for (int nb = 0; nb < 4; nb++)
            #pragma unroll
            for (int q = 0; q < 4; q++) acc[mt][nb][q] = 0.f;

    load_stage(0);
    load_stage(1);

    // precompute ldmatrix lane addressing pieces
    int a_row = (lane & 15);               // + wm*64 + mt*16
    int a_kh  = lane >> 4;                 // k-chunk half
    int b_row = (lane & 7) + ((lane >> 4) & 1) * 8;   // + wn*32 + np*16
    int b_kh  = (lane >> 3) & 1;

    for (int ch = 0; ch < NCH; ch++) {
        asm volatile("cp.async.wait_group 1;" ::: "memory");
        __syncthreads();
        if (ch + 2 < NCH) load_stage(ch + 2);
        else asm volatile("cp.async.commit_group;");

        uint32_t sA = smb + (ch % STAGES) * STAGE_BYTES;
        uint32_t sB = sA + 8192;

        #pragma unroll
        for (int kt = 0; kt < 2; kt++) {
            uint32_t a[4][4], b[2][4];
            #pragma unroll
            for (int mt = 0; mt < 4; mt++) {
                int row = wm*64 + mt*16 + a_row;
                int cc  = kt*2 + a_kh;
                ldsm_x4(a[mt], sA + row*64 + (((uint32_t)(cc ^ (row & 3))) << 4));
            }
            #pragma unroll
            for (int np = 0; np < 2; np++) {
                int row = wn*32 + np*16 + b_row;
                int cc  = kt*2 + b_kh;
                ldsm_x4(b[np], sB + row*64 + (((uint32_t)(cc ^ (row & 3))) << 4));
            }
            #pragma unroll
            for (int mt = 0; mt < 4; mt++)
                #pragma unroll
                for (int nb = 0; nb < 4; nb++)
                    mma_bf16(acc[mt][nb], a[mt], &b[nb >> 1][(nb & 1) * 2]);
        }
    }

    // epilogue: c0,c1 -> row g, c2,c3 -> row g+8; cols 2*(lane%4)+{0,1}
    int gid = lane >> 2, c2 = (lane & 3) * 2;
    #pragma unroll
    for (int mt = 0; mt < 4; mt++) {
        int o = ob*128 + wm*64 + mt*16 + gid;
        float* base0 = out + ((size_t)(n*CI_ + o    ))*HW + p0 + wn*32 + c2;
        float* base1 = out + ((size_t)(n*CI_ + o + 8))*HW + p0 + wn*32 + c2;
        #pragma unroll
        for (int nb = 0; nb < 4; nb++) {
            *(float2*)(base0 + nb*8) = make_float2(acc[mt][nb][0], acc[mt][nb][1]);
            *(float2*)(base1 + nb*8) = make_float2(acc[mt][nb][2], acc[mt][nb][3]);
        }
    }
}

// ============================================================
extern "C" void kernel_launch(void* const* d_in, const int* in_sizes, int n_in,
                              void* d_out, int out_size) {
    const float* x   = (const float*)d_in[0];
    const float* lat = (const float*)d_in[1];
    const float* tw  = (const float*)d_in[2];
    const float* w1  = (const float*)d_in[3];
    const float* b1  = (const float*)d_in[4];
    const float* w2  = (const float*)d_in[5];
    const float* b2  = (const float*)d_in[6];
    float* out = (float*)d_out;

    cudaFuncSetAttribute(mma_kernel, cudaFuncAttributeMaxDynamicSharedMemorySize, MMA_SMEM);

    offset_kernel<<<1, 256>>>(lat, w1, b1, w2, b2);
    split_a_kernel<<<CI_, 256>>>(tw);
    transconv_kernel<<<dim3(16, 16, NB), 128>>>(x, tw);
    build_st_kernel<<<dim3(128, 16, NB), 128>>>();
    mma_kernel<<<dim3(128, 2, NB), 256, MMA_SMEM>>>(out);
}

// round 17
// speedup vs baseline: 1.7818x; 1.2049x over previous
#include <cuda_runtime.h>
#include <cuda_fp16.h>
#include <math.h>
#include <stdint.h>

#define NB   2
#define CI_  256
#define CO_  128
#define H0   64
#define W0   64
#define HH   128
#define WW   128
#define KKT  9
#define KGEMM (CO_*KKT)   // 1152
#define HW   (HH*WW)      // 16384

// ---- scratch (device globals; no allocations anywhere) ----
__device__ float g_up[NB*CO_*HH*WW];                  // 16 MB
__device__ __half g_Sh[(size_t)NB*HW*KGEMM];          // 75.5 MB  St hi  [p][k] K-major fp16
__device__ __half g_Ah[CI_*KGEMM];                    // 0.59 MB  W hi [o][k] fp16
__device__ __half g_Al[CI_*KGEMM];                    // 0.59 MB  W residual fp16
__device__ int   g_ab[NB*KKT*2];
__device__ float g_w4[NB*KKT*4];

// ======================= PTX helpers (baseline ISA only, sm_80+) =======================
__device__ __forceinline__ uint32_t smem_u32(const void* p) {
    uint32_t a;
    asm("{ .reg .u64 t; cvta.to.shared.u64 t, %1; cvt.u32.u64 %0, t; }" : "=r"(a) : "l"(p));
    return a;
}
__device__ __forceinline__ void cp_async16(uint32_t dst, const void* src) {
    asm volatile("cp.async.cg.shared.global [%0], [%1], 16;" :: "r"(dst), "l"(src));
}
__device__ __forceinline__ void ldsm_x4(uint32_t* r, uint32_t addr) {
    asm volatile("ldmatrix.sync.aligned.m8n8.x4.shared.b16 {%0,%1,%2,%3}, [%4];"
        : "=r"(r[0]), "=r"(r[1]), "=r"(r[2]), "=r"(r[3]) : "r"(addr));
}
__device__ __forceinline__ void mma_f16(float* d, const uint32_t* a, const uint32_t* b) {
    asm volatile("mma.sync.aligned.m16n8k16.row.col.f32.f16.f16.f32 "
        "{%0,%1,%2,%3}, {%4,%5,%6,%7}, {%8,%9}, {%0,%1,%2,%3};"
        : "+f"(d[0]), "+f"(d[1]), "+f"(d[2]), "+f"(d[3])
        : "r"(a[0]), "r"(a[1]), "r"(a[2]), "r"(a[3]), "r"(b[0]), "r"(b[1]));
}

// ============================================================
// 1) offsets
// ============================================================
__global__ void offset_kernel(const float* __restrict__ lat_g,
                              const float* __restrict__ w1,
                              const float* __restrict__ b1,
                              const float* __restrict__ w2,
                              const float* __restrict__ b2) {
    __shared__ float lat[NB*CO_];
    __shared__ float hsm[NB*64];
    __shared__ float off[NB*18];
    int t = threadIdx.x;
    if (t < NB*CO_) lat[t] = lat_g[t];
    __syncthreads();
    if (t < NB*64) {
        int n = t >> 6, c = t & 63;
        float s = b1[c];
        const float* lp = &lat[n*CO_];
        #pragma unroll 4
        for (int i = 0; i < CO_; i++) s += lp[i] * w1[c*(CO_*9) + i*9 + 4];
        hsm[t] = fmaxf(s, 0.f);
    }
    __syncthreads();
    if (t < NB*18) {
        int n = t / 18, j = t % 18;
        float s = b2[j];
        const float* hp = &hsm[n*64];
        #pragma unroll 4
        for (int c = 0; c < 64; c++) s += hp[c] * w2[j*(64*9) + c*9 + 4];
        off[n*18 + j] = tanhf(s);
    }
    __syncthreads();
    if (t < NB*KKT) {
        int n  = t / KKT;
        int kk = t % KKT;
        int ky = kk / 3, kx = kk % 3;
        float oy = off[n*18 + kk*2 + 0];
        float ox = off[n*18 + kk*2 + 1];
        float fy = floorf(oy), fx = floorf(ox);
        float dy = oy - fy,    dx = ox - fx;
        g_ab[t*2+0] = ky - 1 + (int)fy;
        g_ab[t*2+1] = kx - 1 + (int)fx;
        g_w4[t*4+0] = (1.f-dy)*(1.f-dx);
        g_w4[t*4+1] = (1.f-dy)*dx;
        g_w4[t*4+2] = dy*(1.f-dx);
        g_w4[t*4+3] = dy*dx;
    }
}

// ============================================================
// 2) split trans_w [o][k] fp32 -> Ah (fp16) + Al (fp16 residual): Ah+Al == W to ~fp32
// ============================================================
__global__ void split_a_kernel(const float* __restrict__ tw) {
    int o = blockIdx.x;
    for (int k = threadIdx.x; k < KGEMM; k += blockDim.x) {
        float w = tw[o*KGEMM + k];
        __half h = __float2half(w);
        __half l = __float2half(w - __half2float(h));
        g_Ah[o*KGEMM + k] = h;
        g_Al[o*KGEMM + k] = l;
    }
}

// ============================================================
// 3) transposed conv (parity decomposition) -> g_up   [unchanged, proven]
// ============================================================
__global__ __launch_bounds__(128) void transconv_kernel(const float* __restrict__ x,
                                                        const float* __restrict__ tw) {
    __shared__ float xs[8][17][18];
    __shared__ float ws[8][8][9];
    int n    = blockIdx.z;
    int cob  = blockIdx.y;
    int tile = blockIdx.x;
    int ty0 = (tile >> 2) * 16;
    int tx0 = (tile &  3) * 16;
    int t = threadIdx.x;
    int qx = t & 15, qyb = t >> 4;

    float acc[2][8][4];
    #pragma unroll
    for (int q = 0; q < 2; q++)
        #pragma unroll
        for (int co = 0; co < 8; co++)
            #pragma unroll
            for (int s = 0; s < 4; s++) acc[q][co][s] = 0.f;

    for (int cic = 0; cic < CI_; cic += 8) {
        for (int l = t; l < 8*17*17; l += 128) {
            int ci = l / 289, rem = l % 289, r = rem / 17, s = rem % 17;
            int yy = ty0 + r, xx = tx0 + s;
            float v = 0.f;
            if (yy < H0 && xx < W0)
                v = x[((n*CI_ + cic + ci)*H0 + yy)*W0 + xx];
            xs[ci][r][s] = v;
        }
        for (int l = t; l < 8*8*9; l += 128) {
            int ci = l / 72, rem = l % 72, co = rem / 9, tap = rem % 9;
            ws[ci][co][tap] = tw[(cic+ci)*KGEMM + (cob*8+co)*9 + tap];
        }
        __syncthreads();

        #pragma unroll
        for (int ci = 0; ci < 8; ci++) {
            float Av[2], Bv[2], Cv[2], Dv[2];
            #pragma unroll
            for (int q = 0; q < 2; q++) {
                int qy = qyb + q*8;
                Av[q] = xs[ci][qy  ][qx  ];
                Bv[q] = xs[ci][qy  ][qx+1];
                Cv[q] = xs[ci][qy+1][qx  ];
                Dv[q] = xs[ci][qy+1][qx+1];
            }
            #pragma unroll
            for (int co = 0; co < 8; co++) {
                float u0 = ws[ci][co][0], u1 = ws[ci][co][1], u2 = ws[ci][co][2];
                float u3 = ws[ci][co][3], u4 = ws[ci][co][4], u5 = ws[ci][co][5];
                float u6 = ws[ci][co][6], u7 = ws[ci][co][7], u8 = ws[ci][co][8];
                #pragma unroll
                for (int q = 0; q < 2; q++) {
                    acc[q][co][0] = fmaf(Av[q], u4, acc[q][co][0]);
                    acc[q][co][1] = fmaf(Bv[q], u3, fmaf(Av[q], u5, acc[q][co][1]));
                    acc[q][co][2] = fmaf(Cv[q], u1, fmaf(Av[q], u7, acc[q][co][2]));
                    acc[q][co][3] = fmaf(Dv[q], u0, fmaf(Cv[q], u2,
                                    fmaf(Bv[q], u6, fmaf(Av[q], u8, acc[q][co][3]))));
                }
            }
        }
        __syncthreads();
    }

    #pragma unroll
    for (int q = 0; q < 2; q++) {
        int Y = (ty0 + qyb + q*8) * 2;
        int X = (tx0 + qx) * 2;
        #pragma unroll
        for (int co = 0; co < 8; co++) {
            float* up = &g_up[((n*CO_ + cob*8+co)*HH + Y)*WW + X];
            *(float2*)(up)      = make_float2(acc[q][co][0], acc[q][co][1]);
            *(float2*)(up + WW) = make_float2(acc[q][co][2], acc[q][co][3]);
        }
    }
}

// ============================================================
// 4) build St (transposed, K-major, fp16 hi only)
//    St[n*HW + y*128 + p][c*9+kk] = bilinear sample of up[n][c] at (y,p)
// ============================================================
__global__ __launch_bounds__(128) void build_st_kernel() {
    __shared__ float R[8][5][132];
    __shared__ float wv[KKT][4];
    __shared__ int   av[KKT], bv[KKT];

    int y  = blockIdx.x;
    int cc = blockIdx.y;          // channel chunk (8 ch)
    int n  = blockIdx.z;
    int t  = threadIdx.x;         // pixel p
    int c0 = cc * 8;

    if (t < KKT) {
        int id = n*KKT + t;
        av[t] = g_ab[id*2+0];
        bv[t] = g_ab[id*2+1];
        wv[t][0] = g_w4[id*4+0]; wv[t][1] = g_w4[id*4+1];
        wv[t][2] = g_w4[id*4+2]; wv[t][3] = g_w4[id*4+3];
    }
    for (int l = t; l < 8*5*132; l += 128) {
        int c = l / 660, rem = l % 660, d = rem / 132, j = rem % 132;
        int ry = y + d - 2, xg = j - 2;
        float v = 0.f;
        if ((unsigned)ry < (unsigned)HH && (unsigned)xg < (unsigned)WW)
            v = g_up[((n*CO_ + c0 + c)*HH + ry)*WW + xg];
        R[c][d][j] = v;
    }
    __syncthreads();

    uint32_t hbuf[36];
    #pragma unroll
    for (int c = 0; c < 8; c++) {
        #pragma unroll
        for (int kk = 0; kk < 9; kk++) {
            int d0 = av[kk] + 2;
            int j0 = t + bv[kk] + 2;
            float s = fmaf(wv[kk][0], R[c][d0  ][j0],
                      fmaf(wv[kk][1], R[c][d0  ][j0+1],
                      fmaf(wv[kk][2], R[c][d0+1][j0],
                           wv[kk][3]* R[c][d0+1][j0+1])));
            __half h = __float2half(s);
            unsigned short hu = *(unsigned short*)&h;
            int k = c*9 + kk;
            if (k & 1) hbuf[k>>1] |= (uint32_t)hu << 16;
            else       hbuf[k>>1]  = hu;
        }
    }

    size_t rowbase = ((size_t)(n*HW + y*128 + t))*KGEMM + c0*9;
    uint4* hdst = (uint4*)&g_Sh[rowbase];
    #pragma unroll
    for (int q = 0; q < 9; q++)
        hdst[q] = make_uint4(hbuf[q*4], hbuf[q*4+1], hbuf[q*4+2], hbuf[q*4+3]);
}

// ============================================================
// 5) mma.sync fp16 GEMM, 2-term split: out = Ah·Sh + Al·Sh  (= W·Sh exactly in W)
//    CTA 128(o) x 128(p), BK=32, 8 warps (2x4), warp tile 64x32.
//    3-stage cp.async ring, XOR-swizzled 16B chunks for ldmatrix.
// ============================================================
#define STAGES 3
#define NCH 72                  // 2 passes * (1152/32)
#define STAGE_BYTES 16384       // A 8K + B 8K
#define MMA_SMEM (STAGES*STAGE_BYTES)   // 49152

__global__ __launch_bounds__(256, 2) void mma_kernel(float* __restrict__ out) {
    extern __shared__ char smem[];
    uint32_t smb = smem_u32(smem);
    int t = threadIdx.x, lane = t & 31, w = t >> 5;
    int wm = w >> 2, wn = w & 3;           // 2 x 4 warp grid
    int p0 = blockIdx.x * 128;
    int ob = blockIdx.y;                   // o-block of 128
    int n  = blockIdx.z;

    const size_t Aoff = (size_t)ob*128*KGEMM;
    const size_t Boff = (size_t)(n*HW + p0)*KGEMM;

    int rowA[2], colA[2];
    #pragma unroll
    for (int i = 0; i < 2; i++) {
        int u = t + i*256;
        rowA[i] = u >> 2; colA[i] = u & 3;
    }

    auto load_stage = [&](int ch) {
        int pass = ch / 36, k0 = (ch % 36) * 32;
        const __half* As = ((pass == 1) ? g_Al : g_Ah) + Aoff;
        const __half* Bs = g_Sh + Boff;
        uint32_t sA = smb + (ch % STAGES) * STAGE_BYTES;
        uint32_t sB = sA + 8192;
        #pragma unroll
        for (int i = 0; i < 2; i++) {
            int row = rowA[i], c = colA[i];
            uint32_t sw = ((uint32_t)(c ^ (row & 3))) << 4;
            cp_async16(sA + row*64 + sw, As + (size_t)row*KGEMM + k0 + c*8);
            cp_async16(sB + row*64 + sw, Bs + (size_t)row*KGEMM + k0 + c*8);
        }
        asm volatile("cp.async.commit_group;");
    };

    float acc[4][4][4];
    #pragma unroll
    for (int mt = 0; mt < 4; mt++)
        #pragma unroll
        for (int nb = 0; nb < 4; nb++)
            #pragma unroll
            for (int q = 0; q < 4; q++) acc[mt][nb][q] = 0.f;

    load_stage(0);
    load_stage(1);

    int a_row = (lane & 15);
    int a_kh  = lane >> 4;
    int b_row = (lane & 7) + ((lane >> 4) & 1) * 8;
    int b_kh  = (lane >> 3) & 1;

    for (int ch = 0; ch < NCH; ch++) {
        asm volatile("cp.async.wait_group 1;" ::: "memory");
        __syncthreads();
        if (ch + 2 < NCH) load_stage(ch + 2);
        else asm volatile("cp.async.commit_group;");

        uint32_t sA = smb + (ch % STAGES) * STAGE_BYTES;
        uint32_t sB = sA + 8192;

        #pragma unroll
        for (int kt = 0; kt < 2; kt++) {
            uint32_t a[4][4], b[2][4];
            #pragma unroll
            for (int mt = 0; mt < 4; mt++) {
                int row = wm*64 + mt*16 + a_row;
                int cc  = kt*2 + a_kh;
                ldsm_x4(a[mt], sA + row*64 + (((uint32_t)(cc ^ (row & 3))) << 4));
            }
            #pragma unroll
            for (int np = 0; np < 2; np++) {
                int row = wn*32 + np*16 + b_row;
                int cc  = kt*2 + b_kh;
                ldsm_x4(b[np], sB + row*64 + (((uint32_t)(cc ^ (row & 3))) << 4));
            }
            #pragma unroll
            for (int mt = 0; mt < 4; mt++)
                #pragma unroll
                for (int nb = 0; nb < 4; nb++)
                    mma_f16(acc[mt][nb], a[mt], &b[nb >> 1][(nb & 1) * 2]);
        }
    }

    int gid = lane >> 2, c2 = (lane & 3) * 2;
    #pragma unroll
    for (int mt = 0; mt < 4; mt++) {
        int o = ob*128 + wm*64 + mt*16 + gid;
        float* base0 = out + ((size_t)(n*CI_ + o    ))*HW + p0 + wn*32 + c2;
        float* base1 = out + ((size_t)(n*CI_ + o + 8))*HW + p0 + wn*32 + c2;
        #pragma unroll
        for (int nb = 0; nb < 4; nb++) {
            *(float2*)(base0 + nb*8) = make_float2(acc[mt][nb][0], acc[mt][nb][1]);
            *(float2*)(base1 + nb*8) = make_float2(acc[mt][nb][2], acc[mt][nb][3]);
        }
    }
}

// ============================================================
extern "C" void kernel_launch(void* const* d_in, const int* in_sizes, int n_in,
                              void* d_out, int out_size) {
    const float* x   = (const float*)d_in[0];
    const float* lat = (const float*)d_in[1];
    const float* tw  = (const float*)d_in[2];
    const float* w1  = (const float*)d_in[3];
    const float* b1  = (const float*)d_in[4];
    const float* w2  = (const float*)d_in[5];
    const float* b2  = (const float*)d_in[6];
    float* out = (float*)d_out;

    cudaFuncSetAttribute(mma_kernel, cudaFuncAttributeMaxDynamicSharedMemorySize, MMA_SMEM);

    offset_kernel<<<1, 256>>>(lat, w1, b1, w2, b2);
    split_a_kernel<<<CI_, 256>>>(tw);
    transconv_kernel<<<dim3(16, 16, NB), 128>>>(x, tw);
    build_st_kernel<<<dim3(128, 16, NB), 128>>>();
    mma_kernel<<<dim3(128, 2, NB), 256, MMA_SMEM>>>(out);
}